// round 1
// baseline (speedup 1.0000x reference)
#include <cuda_runtime.h>

// out[b, a*16+c, d, l] = sum_k s[b, (c-a)%16, l, k] * t[b, c, l, d-k]
//   (linear convolution, since 63+63-1 = 125 <= 128 => FFT result has no wrap)
// s,t: (32, 16, 64, 63) fp32.  out: (32, 256, 128, 64) fp32.
//
// Block = (lbase, c, b): computes all 16 m (= all 16 a) for one (b, c, l-tile of 16).
// Thread (l_off = tid&15, d_oct = tid>>4): 8 d values, all 16 m (two halves of 8),
// accumulators packed 2 m's per fma.rn.f32x2.

#define L_TILE   16
#define S_STRIDE 1010   // 16*63=1008 used; 1010 mod 32 = 18 -> conflict-free, 8B-aligned rows
#define T_STRIDE 195    // 190 used;         195 mod 32 = 3  -> conflict-free for l x d_oct footprint
#define SMEM_FLOATS (L_TILE * S_STRIDE + L_TILE * T_STRIDE)
#define SMEM_BYTES  (SMEM_FLOATS * 4)

typedef unsigned long long u64;

__global__ __launch_bounds__(256, 2)
void conv_all_pairs(const float* __restrict__ s_g,
                    const float* __restrict__ t_g,
                    float* __restrict__ out) {
    extern __shared__ float sm[];
    float* s_sh = sm;                      // [L_TILE][S_STRIDE], layout s_sh[l][k*16 + m]
    float* t_sh = sm + L_TILE * S_STRIDE;  // [L_TILE][T_STRIDE], layout t_sh[l][62 + j] (zero-padded)

    const int lbase = blockIdx.x * L_TILE;
    const int c     = blockIdx.y;
    const int b     = blockIdx.z;
    const int tid   = threadIdx.x;

    // ---- stage t (zero-padded: j in [0,63) live, rest 0) ----
    for (int i = tid; i < L_TILE * T_STRIDE; i += 256) t_sh[i] = 0.0f;
    __syncthreads();
    {
        const float* tg = t_g + ((size_t)(b * 16 + c) * 64 + lbase) * 63;
        for (int i = tid; i < L_TILE * 63; i += 256) {
            int l = i / 63, k = i - l * 63;
            t_sh[l * T_STRIDE + 62 + k] = tg[l * 63 + k];
        }
    }
    // ---- stage s for ALL 16 m, transposed so m is contiguous (aligned float2 pairs) ----
    {
        const float* sg = s_g + ((size_t)b * 16 * 64 + lbase) * 63;
        for (int i = tid; i < 16 * L_TILE * 63; i += 256) {
            int m = i / (L_TILE * 63);
            int r = i - m * (L_TILE * 63);
            int l = r / 63, k = r - l * 63;
            s_sh[l * S_STRIDE + k * 16 + m] = sg[(m * 64 + l) * 63 + k];
        }
    }
    __syncthreads();

    const int l_off = tid & 15;
    const int d_oct = tid >> 4;        // 0..15
    const int dbase = d_oct * 8;

    const float* srow = s_sh + l_off * S_STRIDE;
    const float* trow = t_sh + l_off * T_STRIDE + 62 + dbase;  // trow[dd - k] = t_pad[d - k]

    #pragma unroll 1
    for (int mh = 0; mh < 2; mh++) {                 // two halves of 8 m's (register pressure)
        u64 acc[4][8];                               // [m-pair][dd], each u64 = (f32 m_even, f32 m_odd)
        #pragma unroll
        for (int mp = 0; mp < 4; mp++)
            #pragma unroll
            for (int dd = 0; dd < 8; dd++) acc[mp][dd] = 0ULL;

        #pragma unroll 1
        for (int k = 0; k < 63; k++) {
            // 4 aligned 8B loads: s pairs (m = mh*8 + 2mp, 2mp+1) — amortized over 8 dd
            u64 s2[4];
            const u64* sp = (const u64*)(srow + k * 16 + mh * 8);
            #pragma unroll
            for (int mp = 0; mp < 4; mp++) s2[mp] = sp[mp];

            const float* tk = trow - k;
            #pragma unroll
            for (int dd = 0; dd < 8; dd++) {
                u64 t2;
                asm("mov.b64 %0, {%1, %1};" : "=l"(t2) : "r"(__float_as_uint(tk[dd])));
                #pragma unroll
                for (int mp = 0; mp < 4; mp++)
                    asm("fma.rn.f32x2 %0, %1, %2, %0;"
                        : "+l"(acc[mp][dd]) : "l"(s2[mp]), "l"(t2));
            }
        }

        // ---- store: lanes vary l fastest -> 64B-coalesced segments ----
        #pragma unroll
        for (int mp = 0; mp < 4; mp++) {
            #pragma unroll
            for (int hi = 0; hi < 2; hi++) {
                int m = mh * 8 + mp * 2 + hi;
                int a = (c - m) & 15;
                float* ob = out + (((size_t)(b * 256 + a * 16 + c) * 128 + dbase) * 64)
                          + lbase + l_off;
                #pragma unroll
                for (int dd = 0; dd < 8; dd++) {
                    unsigned u = hi ? (unsigned)(acc[mp][dd] >> 32)
                                    : (unsigned)(acc[mp][dd]);
                    ob[dd * 64] = __uint_as_float(u);
                }
            }
        }
    }
}

extern "C" void kernel_launch(void* const* d_in, const int* in_sizes, int n_in,
                              void* d_out, int out_size) {
    const float* s = (const float*)d_in[0];
    const float* t = (const float*)d_in[1];
    float* out = (float*)d_out;

    cudaFuncSetAttribute(conv_all_pairs,
                         cudaFuncAttributeMaxDynamicSharedMemorySize, SMEM_BYTES);

    dim3 grid(64 / L_TILE, 16, 32);   // (l-tile, c, b) = 2048 blocks
    conv_all_pairs<<<grid, 256, SMEM_BYTES>>>(s, t, out);
}

// round 2
// speedup vs baseline: 1.0774x; 1.0774x over previous
#include <cuda_runtime.h>

// out[b, a*16+c, d, l] = sum_k s[b, (c-a)%16, l, k] * t[b, c, l, d-k]
//   (linear convolution: 63+63-1 = 125 <= 128 => the reference FFT has no wrap)
// s,t: (32, 16, 64, 63) fp32.  out: (32, 256, 128, 64) fp32.
//
// Block = (l-tile of 16, c, b). Thread (l_off = tid&15, d_oct = tid>>4) owns
// 8 d values for all 16 m (two halves of 8 m), accumulators packed 2 m's per
// fma.rn.f32x2. t values are kept in a rolling register window (duplicated
// u64 packs): ONE new LDS.32 per k-step instead of 8, rotation free via
// compile-time modular indexing in the 8x-unrolled k loop.

#define L_TILE   16
#define S_STRIDE 1026   // 64*16=1024 used; 1026 mod 32 = 2 -> conflict-free, 8B-aligned rows
#define T_STRIDE 195    // 195 mod 32 = 3 -> conflict-free for the warp's l x d_oct footprint
#define T_BASE   64     // t[k] stored at column T_BASE+k; index T_BASE+dbase+j-k stays >= 0 for k<=64
#define SMEM_FLOATS (L_TILE * S_STRIDE + L_TILE * T_STRIDE)
#define SMEM_BYTES  (SMEM_FLOATS * 4)

typedef unsigned long long u64;

__device__ __forceinline__ u64 dup2(float x) {
    u64 r;
    asm("mov.b64 %0, {%1, %1};" : "=l"(r) : "r"(__float_as_uint(x)));
    return r;
}

__global__ __launch_bounds__(256, 2)
void conv_all_pairs(const float* __restrict__ s_g,
                    const float* __restrict__ t_g,
                    float* __restrict__ out) {
    extern __shared__ float sm[];
    float* s_sh = sm;                      // [L_TILE][S_STRIDE], s_sh[l][k*16 + m], k in [0,64) (k=63 zero)
    float* t_sh = sm + L_TILE * S_STRIDE;  // [L_TILE][T_STRIDE], t_sh[l][T_BASE + k], zero elsewhere

    const int lbase = blockIdx.x * L_TILE;
    const int c     = blockIdx.y;
    const int b     = blockIdx.z;
    const int tid   = threadIdx.x;

    // ---- zero both regions (zero-padding is load-bearing for the k=64 pad & window look-ahead) ----
    for (int i = tid; i < SMEM_FLOATS; i += 256) sm[i] = 0.0f;
    __syncthreads();

    // ---- stage t ----
    {
        const float* tg = t_g + ((size_t)(b * 16 + c) * 64 + lbase) * 63;
        for (int i = tid; i < L_TILE * 63; i += 256) {
            int l = i / 63, k = i - l * 63;
            t_sh[l * T_STRIDE + T_BASE + k] = tg[l * 63 + k];
        }
    }
    // ---- stage s for ALL 16 m, m contiguous (aligned float2 pairs) ----
    {
        const float* sg = s_g + ((size_t)b * 16 * 64 + lbase) * 63;
        for (int i = tid; i < 16 * L_TILE * 63; i += 256) {
            int m = i / (L_TILE * 63);
            int r = i - m * (L_TILE * 63);
            int l = r / 63, k = r - l * 63;
            s_sh[l * S_STRIDE + k * 16 + m] = sg[(m * 64 + l) * 63 + k];
        }
    }
    __syncthreads();

    const int l_off = tid & 15;
    const int d_oct = tid >> 4;        // 0..15
    const int dbase = d_oct * 8;

    const float* srow = s_sh + l_off * S_STRIDE;
    const float* trow = t_sh + l_off * T_STRIDE + T_BASE + dbase;  // trow[j - k] = t_pad[dbase + j - k]

    #pragma unroll 1
    for (int mh = 0; mh < 2; mh++) {                 // two halves of 8 m's (register pressure)
        u64 acc[4][8];                               // [m-pair][dd]: (f32 m_even, f32 m_odd)
        #pragma unroll
        for (int mp = 0; mp < 4; mp++)
            #pragma unroll
            for (int dd = 0; dd < 8; dd++) acc[mp][dd] = 0ULL;

        // rolling window: phys w[(j - k) & 7] == dup(trow[j - k]) for logical j = 0..7
        u64 w[8];
        #pragma unroll
        for (int j = 0; j < 8; j++) w[j] = dup2(trow[j]);

        #pragma unroll 1
        for (int kb = 0; kb < 64; kb += 8) {
            #pragma unroll
            for (int kk = 0; kk < 8; kk++) {
                const int k = kb + kk;

                // 4 aligned 8B loads: s pairs (m = mh*8 + 2mp, 2mp+1), amortized over 8 dd
                u64 s2[4];
                const u64* sp = (const u64*)(srow + k * 16 + mh * 8);
                #pragma unroll
                for (int mp = 0; mp < 4; mp++) s2[mp] = sp[mp];

                #pragma unroll
                for (int dd = 0; dd < 8; dd++) {
                    const u64 t2 = w[(dd - kk) & 7];   // kb % 8 == 0 -> compile-time index
                    #pragma unroll
                    for (int mp = 0; mp < 4; mp++)
                        asm("fma.rn.f32x2 %0, %1, %2, %0;"
                            : "+l"(acc[mp][dd]) : "l"(s2[mp]), "l"(t2));
                }

                // look-ahead: insert t value for step k+1 at logical j=0.
                // At k=63 this reads t_sh[l*T_STRIDE + dbase] (valid, zero, unused).
                w[(-(kk + 1)) & 7] = dup2(trow[-(k + 1)]);
            }
        }

        // ---- store: lanes vary l fastest -> 64B-coalesced segments ----
        #pragma unroll
        for (int mp = 0; mp < 4; mp++) {
            #pragma unroll
            for (int hi = 0; hi < 2; hi++) {
                int m = mh * 8 + mp * 2 + hi;
                int a = (c - m) & 15;
                float* ob = out + (((size_t)(b * 256 + a * 16 + c) * 128 + dbase) * 64)
                          + lbase + l_off;
                #pragma unroll
                for (int dd = 0; dd < 8; dd++) {
                    unsigned u = hi ? (unsigned)(acc[mp][dd] >> 32)
                                    : (unsigned)(acc[mp][dd]);
                    ob[dd * 64] = __uint_as_float(u);
                }
            }
        }
    }
}

extern "C" void kernel_launch(void* const* d_in, const int* in_sizes, int n_in,
                              void* d_out, int out_size) {
    const float* s = (const float*)d_in[0];
    const float* t = (const float*)d_in[1];
    float* out = (float*)d_out;

    cudaFuncSetAttribute(conv_all_pairs,
                         cudaFuncAttributeMaxDynamicSharedMemorySize, SMEM_BYTES);

    dim3 grid(64 / L_TILE, 16, 32);   // (l-tile, c, b) = 2048 blocks
    conv_all_pairs<<<grid, 256, SMEM_BYTES>>>(s, t, out);
}

// round 3
// speedup vs baseline: 1.3663x; 1.2682x over previous
#include <cuda_runtime.h>

// out[b, a*16+c, d, l] = sum_k s[b, (c-a)%16, l, k] * t[b, c, l, d-k]
//   (linear convolution: 63+63-1 = 125 <= 128 => the reference FFT has no wrap)
// s,t: (32, 16, 64, 63) fp32.  out: (32, 256, 128, 64) fp32.
//
// Block = (l-tile of 8, c, b), 256 threads, 3 CTAs/SM.
// Thread (l_off = tid&7, d_quad = tid>>3) owns 4 d values x 16 m
// (two mh passes of 8 m), acc packed 2 m per fma.rn.f32x2 (16 u64 = 32 regs).
// Warp = 8 l x 4 consecutive d-quads -> warp-uniform k block-range
// [max(0,16w-64), min(64,16w+16)) skips the provably-zero k blocks (saves 37.5%
// of FFMA2s). s prefetched via double-buffered ld.shared.v2.u64; t kept in a
// 4-deep rolling register window (1 LDS.32 + dup per k, rotation compile-time).

#define L_TILE   8
#define S_STRIDE 1044   // 65*16=1040 used; 16B-aligned rows; 1044 mod 32 = 20 -> conflict-free
#define T_STRIDE 195    // 195 mod 32 = 3
#define T_BASE   64     // t[k] at column T_BASE+k; window index stays >= 0 for k <= 64
#define SMEM_FLOATS (L_TILE * S_STRIDE + L_TILE * T_STRIDE)
#define SMEM_BYTES  (SMEM_FLOATS * 4)   // 39648 B -> 3 CTAs/SM

typedef unsigned long long u64;

__device__ __forceinline__ u64 dup2(float x) {
    u64 r;
    asm("mov.b64 %0, {%1, %1};" : "=l"(r) : "r"(__float_as_uint(x)));
    return r;
}

__device__ __forceinline__ void load_s4(u64* d, unsigned addr) {
    asm volatile("ld.shared.v2.u64 {%0, %1}, [%2];"
                 : "=l"(d[0]), "=l"(d[1]) : "r"(addr));
    asm volatile("ld.shared.v2.u64 {%0, %1}, [%2];"
                 : "=l"(d[2]), "=l"(d[3]) : "r"(addr + 16));
}

__global__ __launch_bounds__(256, 3)
void conv_all_pairs(const float* __restrict__ s_g,
                    const float* __restrict__ t_g,
                    float* __restrict__ out) {
    extern __shared__ float sm[];
    float* s_sh = sm;                      // [8][S_STRIDE]: s_sh[l][k*16+m], k in [0,65) (63,64 zero)
    float* t_sh = sm + L_TILE * S_STRIDE;  // [8][T_STRIDE]: t_sh[l][T_BASE+k], zero elsewhere

    const int lbase = blockIdx.x * L_TILE;
    const int c     = blockIdx.y;
    const int b     = blockIdx.z;
    const int tid   = threadIdx.x;

    // ---- zero smem (zero padding is load-bearing) ----
    for (int i = tid; i < SMEM_FLOATS; i += 256) sm[i] = 0.0f;
    __syncthreads();

    // ---- stage t ----
    {
        const float* tg = t_g + ((size_t)(b * 16 + c) * 64 + lbase) * 63;
        for (int i = tid; i < L_TILE * 63; i += 256) {
            int l = i / 63, k = i - l * 63;
            t_sh[l * T_STRIDE + T_BASE + k] = tg[l * 63 + k];
        }
    }
    // ---- stage s for all 16 m, m contiguous ----
    {
        const float* sg = s_g + ((size_t)b * 16 * 64 + lbase) * 63;
        for (int i = tid; i < 16 * L_TILE * 63; i += 256) {
            int m = i / (L_TILE * 63);
            int r = i - m * (L_TILE * 63);
            int l = r / 63, k = r - l * 63;
            s_sh[l * S_STRIDE + k * 16 + m] = sg[(m * 64 + l) * 63 + k];
        }
    }
    __syncthreads();

    const int l_off = tid & 7;
    const int dq    = tid >> 3;          // 0..31
    const int wrp   = tid >> 5;          // 0..7 (d-group)
    const int dbase = dq * 4;

    // warp-uniform k block range covering all nonzero contributions
    const int ks = max(0, 16 * wrp - 64);
    const int ke = min(64, 16 * wrp + 16);

    const float* trow = t_sh + l_off * T_STRIDE + T_BASE + dbase;
    const unsigned s_u32 = (unsigned)__cvta_generic_to_shared(s_sh);

    #pragma unroll 1
    for (int mh = 0; mh < 2; mh++) {
        const unsigned srow_a = s_u32 + ((unsigned)(l_off * S_STRIDE + mh * 8) << 2);

        u64 acc[4][4];                    // [m-pair][dd]
        #pragma unroll
        for (int mp = 0; mp < 4; mp++)
            #pragma unroll
            for (int dd = 0; dd < 4; dd++) acc[mp][dd] = 0ULL;

        // rolling window: phys w4[(j - k) & 3] == dup(trow[j - k]); ks % 4 == 0
        u64 w4[4];
        #pragma unroll
        for (int j = 0; j < 4; j++) w4[j] = dup2(trow[j - ks]);

        u64 s2[2][4];
        load_s4(s2[0], srow_a + (unsigned)(ks << 6));   // k=ks -> buffer 0 (ks even)

        #pragma unroll 1
        for (int kb = ks; kb < ke; kb += 8) {
            const float* tp = trow - kb;
            const unsigned sa = srow_a + ((unsigned)kb << 6);
            #pragma unroll
            for (int kk = 0; kk < 8; kk++) {
                load_s4(s2[(kk + 1) & 1], sa + ((unsigned)(kk + 1) << 6));  // prefetch k+1
                const u64* sc = s2[kk & 1];
                #pragma unroll
                for (int dd = 0; dd < 4; dd++) {
                    const u64 t2 = w4[(dd - kk) & 3];
                    #pragma unroll
                    for (int mp = 0; mp < 4; mp++)
                        asm("fma.rn.f32x2 %0, %1, %2, %0;"
                            : "+l"(acc[mp][dd]) : "l"(sc[mp]), "l"(t2));
                }
                // insert t for step k+1 (reads stay in-row: index >= dbase >= 0)
                w4[(-(kk + 1)) & 3] = dup2(tp[-(kk + 1)]);
            }
        }

        // ---- store: lanes vary l fastest -> full 32B sectors ----
        #pragma unroll
        for (int mp = 0; mp < 4; mp++) {
            #pragma unroll
            for (int hi = 0; hi < 2; hi++) {
                int m = mh * 8 + mp * 2 + hi;
                int a = (c - m) & 15;
                float* ob = out + (((size_t)(b * 256 + a * 16 + c) * 128 + dbase) * 64)
                          + lbase + l_off;
                #pragma unroll
                for (int dd = 0; dd < 4; dd++) {
                    unsigned u = hi ? (unsigned)(acc[mp][dd] >> 32)
                                    : (unsigned)(acc[mp][dd]);
                    ob[dd * 64] = __uint_as_float(u);
                }
            }
        }
    }
}

extern "C" void kernel_launch(void* const* d_in, const int* in_sizes, int n_in,
                              void* d_out, int out_size) {
    const float* s = (const float*)d_in[0];
    const float* t = (const float*)d_in[1];
    float* out = (float*)d_out;

    cudaFuncSetAttribute(conv_all_pairs,
                         cudaFuncAttributeMaxDynamicSharedMemorySize, SMEM_BYTES);

    dim3 grid(64 / L_TILE, 16, 32);   // (l-tile, c, b) = 4096 blocks
    conv_all_pairs<<<grid, 256, SMEM_BYTES>>>(s, t, out);
}

// round 4
// speedup vs baseline: 1.3673x; 1.0007x over previous
#include <cuda_runtime.h>

// out[b, a*16+c, d, l] = sum_k s[b, (c-a)%16, l, k] * t[b, c, l, d-k]
//   (linear convolution: 63+63-1 = 125 <= 128 => the reference FFT has no wrap)
// s,t: (32, 16, 64, 63) fp32.  out: (32, 256, 128, 64) fp32.
//
// Block = (l-tile of 8, c, b), 256 threads, 3 CTAs/SM.
// Thread (l_off = tid&7, d_quad = tid>>3) owns 4 d values x 16 m
// (two mh passes of 8 m), acc packed 2 m per fma.rn.f32x2 (16 u64 = 32 regs).
// Warp = 8 l x 4 consecutive d-quads -> warp-uniform k block-range
// [max(0,16w-64), min(64,16w+16)) skips the provably-zero k blocks (saves 37.5%
// of FFMA2s). s prefetched via double-buffered ld.shared.v2.u64; t kept in a
// 4-deep rolling register window (1 LDS.32 + dup per k, rotation compile-time).

#define L_TILE   8
#define S_STRIDE 1044   // 65*16=1040 used; 16B-aligned rows; 1044 mod 32 = 20 -> conflict-free
#define T_STRIDE 195    // 195 mod 32 = 3
#define T_BASE   64     // t[k] at column T_BASE+k; window index stays >= 0 for k <= 64
#define SMEM_FLOATS (L_TILE * S_STRIDE + L_TILE * T_STRIDE)
#define SMEM_BYTES  (SMEM_FLOATS * 4)   // 39648 B -> 3 CTAs/SM

typedef unsigned long long u64;

__device__ __forceinline__ u64 dup2(float x) {
    u64 r;
    asm("mov.b64 %0, {%1, %1};" : "=l"(r) : "r"(__float_as_uint(x)));
    return r;
}

__device__ __forceinline__ void load_s4(u64* d, unsigned addr) {
    asm volatile("ld.shared.v2.u64 {%0, %1}, [%2];"
                 : "=l"(d[0]), "=l"(d[1]) : "r"(addr));
    asm volatile("ld.shared.v2.u64 {%0, %1}, [%2];"
                 : "=l"(d[2]), "=l"(d[3]) : "r"(addr + 16));
}

__global__ __launch_bounds__(256, 3)
void conv_all_pairs(const float* __restrict__ s_g,
                    const float* __restrict__ t_g,
                    float* __restrict__ out) {
    extern __shared__ float sm[];
    float* s_sh = sm;                      // [8][S_STRIDE]: s_sh[l][k*16+m], k in [0,65) (63,64 zero)
    float* t_sh = sm + L_TILE * S_STRIDE;  // [8][T_STRIDE]: t_sh[l][T_BASE+k], zero elsewhere

    const int lbase = blockIdx.x * L_TILE;
    const int c     = blockIdx.y;
    const int b     = blockIdx.z;
    const int tid   = threadIdx.x;

    // ---- zero smem (zero padding is load-bearing) ----
    for (int i = tid; i < SMEM_FLOATS; i += 256) sm[i] = 0.0f;
    __syncthreads();

    // ---- stage t ----
    {
        const float* tg = t_g + ((size_t)(b * 16 + c) * 64 + lbase) * 63;
        for (int i = tid; i < L_TILE * 63; i += 256) {
            int l = i / 63, k = i - l * 63;
            t_sh[l * T_STRIDE + T_BASE + k] = tg[l * 63 + k];
        }
    }
    // ---- stage s for all 16 m, m contiguous ----
    {
        const float* sg = s_g + ((size_t)b * 16 * 64 + lbase) * 63;
        for (int i = tid; i < 16 * L_TILE * 63; i += 256) {
            int m = i / (L_TILE * 63);
            int r = i - m * (L_TILE * 63);
            int l = r / 63, k = r - l * 63;
            s_sh[l * S_STRIDE + k * 16 + m] = sg[(m * 64 + l) * 63 + k];
        }
    }
    __syncthreads();

    const int l_off = tid & 7;
    const int dq    = tid >> 3;          // 0..31
    const int wrp   = tid >> 5;          // 0..7 (d-group)
    const int dbase = dq * 4;

    // warp-uniform k block range covering all nonzero contributions
    const int ks = max(0, 16 * wrp - 64);
    const int ke = min(64, 16 * wrp + 16);

    const float* trow = t_sh + l_off * T_STRIDE + T_BASE + dbase;
    const unsigned s_u32 = (unsigned)__cvta_generic_to_shared(s_sh);

    #pragma unroll 1
    for (int mh = 0; mh < 2; mh++) {
        const unsigned srow_a = s_u32 + ((unsigned)(l_off * S_STRIDE + mh * 8) << 2);

        u64 acc[4][4];                    // [m-pair][dd]
        #pragma unroll
        for (int mp = 0; mp < 4; mp++)
            #pragma unroll
            for (int dd = 0; dd < 4; dd++) acc[mp][dd] = 0ULL;

        // rolling window: phys w4[(j - k) & 3] == dup(trow[j - k]); ks % 4 == 0
        u64 w4[4];
        #pragma unroll
        for (int j = 0; j < 4; j++) w4[j] = dup2(trow[j - ks]);

        u64 s2[2][4];
        load_s4(s2[0], srow_a + (unsigned)(ks << 6));   // k=ks -> buffer 0 (ks even)

        #pragma unroll 1
        for (int kb = ks; kb < ke; kb += 8) {
            const float* tp = trow - kb;
            const unsigned sa = srow_a + ((unsigned)kb << 6);
            #pragma unroll
            for (int kk = 0; kk < 8; kk++) {
                load_s4(s2[(kk + 1) & 1], sa + ((unsigned)(kk + 1) << 6));  // prefetch k+1
                const u64* sc = s2[kk & 1];
                #pragma unroll
                for (int dd = 0; dd < 4; dd++) {
                    const u64 t2 = w4[(dd - kk) & 3];
                    #pragma unroll
                    for (int mp = 0; mp < 4; mp++)
                        asm("fma.rn.f32x2 %0, %1, %2, %0;"
                            : "+l"(acc[mp][dd]) : "l"(sc[mp]), "l"(t2));
                }
                // insert t for step k+1 (reads stay in-row: index >= dbase >= 0)
                w4[(-(kk + 1)) & 3] = dup2(tp[-(kk + 1)]);
            }
        }

        // ---- store: lanes vary l fastest -> full 32B sectors ----
        #pragma unroll
        for (int mp = 0; mp < 4; mp++) {
            #pragma unroll
            for (int hi = 0; hi < 2; hi++) {
                int m = mh * 8 + mp * 2 + hi;
                int a = (c - m) & 15;
                float* ob = out + (((size_t)(b * 256 + a * 16 + c) * 128 + dbase) * 64)
                          + lbase + l_off;
                #pragma unroll
                for (int dd = 0; dd < 4; dd++) {
                    unsigned u = hi ? (unsigned)(acc[mp][dd] >> 32)
                                    : (unsigned)(acc[mp][dd]);
                    ob[dd * 64] = __uint_as_float(u);
                }
            }
        }
    }
}

extern "C" void kernel_launch(void* const* d_in, const int* in_sizes, int n_in,
                              void* d_out, int out_size) {
    const float* s = (const float*)d_in[0];
    const float* t = (const float*)d_in[1];
    float* out = (float*)d_out;

    cudaFuncSetAttribute(conv_all_pairs,
                         cudaFuncAttributeMaxDynamicSharedMemorySize, SMEM_BYTES);

    dim3 grid(64 / L_TILE, 16, 32);   // (l-tile, c, b) = 4096 blocks
    conv_all_pairs<<<grid, 256, SMEM_BYTES>>>(s, t, out);
}